// round 1
// baseline (speedup 1.0000x reference)
#include <cuda_runtime.h>
#include <math.h>

#define B_    4
#define L_    2048
#define HID_  2048
#define H_    16
#define DH_   128
#define QKV_  (3 * HID_)          // 6144
#define PW_   (QKV_ + HID_)       // 8192 (proj width)
#define MTOK_ (B_ * L_)           // 8192
#define EPS_  1e-5f

static __device__ __constant__ float kScale = 0.08838834764831845f; // 1/sqrt(128)

// Scratch (allocation-free rule: __device__ globals)
__device__ float g_proj[(size_t)MTOK_ * PW_];                 // 256 MB
__device__ float g_scores[(size_t)B_ * H_ * L_ * L_];         // 1 GB
__device__ float g_attn[(size_t)MTOK_ * HID_];                // 64 MB

// ---------------------------------------------------------------------------
// Generic fp32 NN GEMM: C[M,N] = A[M,K](lda) * B[K,N](ldb)
// 128x128 block tile, BK=8, 256 threads, 8x8 per-thread micro-tile.
// Requires M%128==0, N%128==0, K%8==0 (true for all uses here).
// ---------------------------------------------------------------------------
__global__ __launch_bounds__(256) void sgemm_nn(
    const float* __restrict__ A, int lda,
    const float* __restrict__ B, int ldb,
    float* __restrict__ C, int ldc,
    int M, int N, int K)
{
    __shared__ float As[8][128];
    __shared__ float Bs[8][128];
    const int tid = threadIdx.x;
    const int bx = blockIdx.x;   // N tile
    const int by = blockIdx.y;   // M tile

    const float* Ab = A + (size_t)by * 128 * lda;
    const float* Bb = B + (size_t)bx * 128;

    const int arow = tid >> 1;          // 0..127
    const int acol = (tid & 1) * 4;     // 0 or 4
    const int brow = tid >> 5;          // 0..7
    const int bcol = (tid & 31) * 4;    // 0..124
    const int ty = tid >> 4;            // 0..15
    const int tx = tid & 15;            // 0..15

    float acc[8][8];
#pragma unroll
    for (int i = 0; i < 8; i++)
#pragma unroll
        for (int j = 0; j < 8; j++) acc[i][j] = 0.f;

    for (int k0 = 0; k0 < K; k0 += 8) {
        float4 av = *(const float4*)(Ab + (size_t)arow * lda + k0 + acol);
        As[acol + 0][arow] = av.x;
        As[acol + 1][arow] = av.y;
        As[acol + 2][arow] = av.z;
        As[acol + 3][arow] = av.w;
        float4 bv = *(const float4*)(Bb + (size_t)(k0 + brow) * ldb + bcol);
        *(float4*)&Bs[brow][bcol] = bv;
        __syncthreads();
#pragma unroll
        for (int kk = 0; kk < 8; ++kk) {
            float ar[8], br[8];
#pragma unroll
            for (int i = 0; i < 8; ++i) ar[i] = As[kk][ty * 8 + i];
#pragma unroll
            for (int j = 0; j < 8; ++j) br[j] = Bs[kk][tx * 8 + j];
#pragma unroll
            for (int i = 0; i < 8; ++i)
#pragma unroll
                for (int j = 0; j < 8; ++j) acc[i][j] += ar[i] * br[j];
        }
        __syncthreads();
    }

    float* Cb = C + (size_t)(by * 128 + ty * 8) * ldc + bx * 128 + tx * 8;
#pragma unroll
    for (int i = 0; i < 8; ++i) {
        *(float4*)(Cb + (size_t)i * ldc + 0) =
            make_float4(acc[i][0], acc[i][1], acc[i][2], acc[i][3]);
        *(float4*)(Cb + (size_t)i * ldc + 4) =
            make_float4(acc[i][4], acc[i][5], acc[i][6], acc[i][7]);
    }
}

// ---------------------------------------------------------------------------
// RMSNorm + RoPE in place on q (heads 0..15) and k (heads 16..31) of g_proj.
// One warp per (token, head2): 128 floats, lane owns {l, l+32, l+64, l+96}.
// ---------------------------------------------------------------------------
__global__ __launch_bounds__(256) void norm_rope_kernel(float* __restrict__ proj)
{
    const int warp = blockIdx.x * 8 + (threadIdx.x >> 5);
    const int lane = threadIdx.x & 31;
    const int head2 = warp & 31;          // 0..31
    const int tok = warp >> 5;            // 0..8191
    const int pos = tok & (L_ - 1);       // position within sequence

    float* x = proj + (size_t)tok * PW_ + (size_t)head2 * DH_;
    float v0 = x[lane];
    float v1 = x[lane + 32];
    float v2 = x[lane + 64];
    float v3 = x[lane + 96];

    float ss = v0 * v0 + v1 * v1 + v2 * v2 + v3 * v3;
#pragma unroll
    for (int o = 16; o; o >>= 1) ss += __shfl_xor_sync(0xffffffffu, ss, o);
    const float r = rsqrtf(ss * (1.0f / DH_) + EPS_);
    v0 *= r; v1 *= r; v2 *= r; v3 *= r;

    // inv_freq[i] = 10000^(-i/64) = exp(-i * ln(10000)/64)
    const float kf = 9.210340371976184f / 64.0f;
    const float fpos = (float)pos;
    const float a0 = fpos * __expf(-kf * (float)lane);
    const float a1 = fpos * __expf(-kf * (float)(lane + 32));
    float c0, s0, c1, s1;
    sincosf(a0, &s0, &c0);
    sincosf(a1, &s1, &c1);

    x[lane]      = v0 * c0 - v2 * s0;
    x[lane + 64] = v0 * s0 + v2 * c0;
    x[lane + 32] = v1 * c1 - v3 * s1;
    x[lane + 96] = v1 * s1 + v3 * c1;
}

// ---------------------------------------------------------------------------
// Scores: S[bh, i, j] = scale * dot(q[b,i,h,:], k[b,j,h,:])  (NT, causal tiles)
// ---------------------------------------------------------------------------
__global__ __launch_bounds__(256) void scores_kernel(
    const float* __restrict__ proj, float* __restrict__ S)
{
    const int bh = blockIdx.z;
    const int b = bh >> 4, h = bh & 15;
    const int j0 = blockIdx.x * 128;
    const int i0 = blockIdx.y * 128;
    if (j0 > i0) return;   // fully above-diagonal tile -> never read

    const float* Q  = proj + (size_t)b * L_ * PW_ + (size_t)h * DH_;
    const float* Km = proj + (size_t)b * L_ * PW_ + (size_t)(H_ + h) * DH_;
    float* C = S + (size_t)bh * L_ * L_;

    __shared__ float As[8][128];
    __shared__ float Bs[8][128];
    const int tid = threadIdx.x;
    const int arow = tid >> 1;
    const int acol = (tid & 1) * 4;
    const int ty = tid >> 4;
    const int tx = tid & 15;

    float acc[8][8];
#pragma unroll
    for (int i = 0; i < 8; i++)
#pragma unroll
        for (int j = 0; j < 8; j++) acc[i][j] = 0.f;

    for (int k0 = 0; k0 < DH_; k0 += 8) {
        float4 av = *(const float4*)(Q + (size_t)(i0 + arow) * PW_ + k0 + acol);
        As[acol + 0][arow] = av.x;
        As[acol + 1][arow] = av.y;
        As[acol + 2][arow] = av.z;
        As[acol + 3][arow] = av.w;
        float4 bv = *(const float4*)(Km + (size_t)(j0 + arow) * PW_ + k0 + acol);
        Bs[acol + 0][arow] = bv.x;
        Bs[acol + 1][arow] = bv.y;
        Bs[acol + 2][arow] = bv.z;
        Bs[acol + 3][arow] = bv.w;
        __syncthreads();
#pragma unroll
        for (int kk = 0; kk < 8; ++kk) {
            float ar[8], br[8];
#pragma unroll
            for (int i = 0; i < 8; ++i) ar[i] = As[kk][ty * 8 + i];
#pragma unroll
            for (int j = 0; j < 8; ++j) br[j] = Bs[kk][tx * 8 + j];
#pragma unroll
            for (int i = 0; i < 8; ++i)
#pragma unroll
                for (int j = 0; j < 8; ++j) acc[i][j] += ar[i] * br[j];
        }
        __syncthreads();
    }

    float* Cb = C + (size_t)(i0 + ty * 8) * L_ + j0 + tx * 8;
#pragma unroll
    for (int i = 0; i < 8; ++i) {
        *(float4*)(Cb + (size_t)i * L_ + 0) =
            make_float4(acc[i][0] * kScale, acc[i][1] * kScale,
                        acc[i][2] * kScale, acc[i][3] * kScale);
        *(float4*)(Cb + (size_t)i * L_ + 4) =
            make_float4(acc[i][4] * kScale, acc[i][5] * kScale,
                        acc[i][6] * kScale, acc[i][7] * kScale);
    }
}

// ---------------------------------------------------------------------------
// Causal softmax per row (only j <= i), then zero-pad up to the row's 128-tile
// boundary so the PV kernel can read whole tiles.
// ---------------------------------------------------------------------------
__global__ __launch_bounds__(256) void softmax_kernel(float* __restrict__ S)
{
    const size_t row = blockIdx.x;                  // bh*L + i
    const int i = (int)(row & (size_t)(L_ - 1));
    float* s = S + row * (size_t)L_;
    const int n = i + 1;
    const int tid = threadIdx.x;
    __shared__ float shm[8];

    float m = -3.402823e38f;
    for (int j = tid; j < n; j += 256) m = fmaxf(m, s[j]);
#pragma unroll
    for (int o = 16; o; o >>= 1) m = fmaxf(m, __shfl_xor_sync(0xffffffffu, m, o));
    if ((tid & 31) == 0) shm[tid >> 5] = m;
    __syncthreads();
    if (tid == 0) {
        float t = shm[0];
#pragma unroll
        for (int w = 1; w < 8; w++) t = fmaxf(t, shm[w]);
        shm[0] = t;
    }
    __syncthreads();
    const float mall = shm[0];
    __syncthreads();

    float sum = 0.f;
    for (int j = tid; j < n; j += 256) {
        float e = __expf(s[j] - mall);
        s[j] = e;
        sum += e;
    }
#pragma unroll
    for (int o = 16; o; o >>= 1) sum += __shfl_xor_sync(0xffffffffu, sum, o);
    if ((tid & 31) == 0) shm[tid >> 5] = sum;
    __syncthreads();
    if (tid == 0) {
        float t = 0.f;
#pragma unroll
        for (int w = 0; w < 8; w++) t += shm[w];
        shm[0] = t;
    }
    __syncthreads();
    const float inv = 1.0f / shm[0];

    for (int j = tid; j < n; j += 256) s[j] *= inv;

    const int pend = (i & ~127) + 128;              // tile-aligned end
    for (int j = n + tid; j < pend; j += 256) s[j] = 0.f;
}

// ---------------------------------------------------------------------------
// O[b,i,h,:] = (P[i,:] @ V) * sigmoid(gate[b,i,h,:]).  NN GEMM, N=128=DH,
// K-loop truncated to causal extent (j < i0+128).
// ---------------------------------------------------------------------------
__global__ __launch_bounds__(256) void pv_kernel(
    const float* __restrict__ proj, const float* __restrict__ S,
    float* __restrict__ attn)
{
    const int i0 = blockIdx.x * 128;
    const int bh = blockIdx.y;
    const int b = bh >> 4, h = bh & 15;

    const float* P = S + (size_t)bh * L_ * L_;                               // [L,L]
    const float* V = proj + (size_t)b * L_ * PW_ + (size_t)(2 * H_ + h) * DH_; // row stride PW_
    const float* G = proj + (size_t)b * L_ * PW_ + QKV_ + (size_t)h * DH_;     // gate
    float* O = attn + (size_t)b * L_ * HID_ + (size_t)h * DH_;

    __shared__ float As[8][128];
    __shared__ float Bs[8][128];
    const int tid = threadIdx.x;
    const int arow = tid >> 1;
    const int acol = (tid & 1) * 4;
    const int brow = tid >> 5;
    const int bcol = (tid & 31) * 4;
    const int ty = tid >> 4;
    const int tx = tid & 15;

    float acc[8][8];
#pragma unroll
    for (int i = 0; i < 8; i++)
#pragma unroll
        for (int j = 0; j < 8; j++) acc[i][j] = 0.f;

    const int kmax = i0 + 128;   // causal: P zero beyond this
    for (int k0 = 0; k0 < kmax; k0 += 8) {
        float4 av = *(const float4*)(P + (size_t)(i0 + arow) * L_ + k0 + acol);
        As[acol + 0][arow] = av.x;
        As[acol + 1][arow] = av.y;
        As[acol + 2][arow] = av.z;
        As[acol + 3][arow] = av.w;
        float4 bv = *(const float4*)(V + (size_t)(k0 + brow) * PW_ + bcol);
        *(float4*)&Bs[brow][bcol] = bv;
        __syncthreads();
#pragma unroll
        for (int kk = 0; kk < 8; ++kk) {
            float ar[8], br[8];
#pragma unroll
            for (int i = 0; i < 8; ++i) ar[i] = As[kk][ty * 8 + i];
#pragma unroll
            for (int j = 0; j < 8; ++j) br[j] = Bs[kk][tx * 8 + j];
#pragma unroll
            for (int i = 0; i < 8; ++i)
#pragma unroll
                for (int j = 0; j < 8; ++j) acc[i][j] += ar[i] * br[j];
        }
        __syncthreads();
    }

    // Epilogue: multiply by sigmoid(gate), store.
#pragma unroll
    for (int i = 0; i < 8; ++i) {
        const int row = i0 + ty * 8 + i;
        const int col = tx * 8;
#pragma unroll
        for (int j4 = 0; j4 < 8; j4 += 4) {
            float4 g = *(const float4*)(G + (size_t)row * PW_ + col + j4);
            float4 v;
            v.x = acc[i][j4 + 0] * (1.0f / (1.0f + __expf(-g.x)));
            v.y = acc[i][j4 + 1] * (1.0f / (1.0f + __expf(-g.y)));
            v.z = acc[i][j4 + 2] * (1.0f / (1.0f + __expf(-g.z)));
            v.w = acc[i][j4 + 3] * (1.0f / (1.0f + __expf(-g.w)));
            *(float4*)(O + (size_t)row * HID_ + col + j4) = v;
        }
    }
}

// ---------------------------------------------------------------------------
extern "C" void kernel_launch(void* const* d_in, const int* in_sizes, int n_in,
                              void* d_out, int out_size)
{
    const float* hidden = (const float*)d_in[0];   // [B,L,HID]
    const float* Wqkvg  = (const float*)d_in[1];   // [HID, PW]
    const float* Wout   = (const float*)d_in[2];   // [HID, HID]
    float* out = (float*)d_out;                    // [B,L,HID]

    float *proj, *scores, *attn;
    cudaGetSymbolAddress((void**)&proj,   g_proj);
    cudaGetSymbolAddress((void**)&scores, g_scores);
    cudaGetSymbolAddress((void**)&attn,   g_attn);

    // 1) proj = hidden @ W_qkvg              [8192,2048]x[2048,8192]
    sgemm_nn<<<dim3(PW_ / 128, MTOK_ / 128), 256>>>(
        hidden, HID_, Wqkvg, PW_, proj, PW_, MTOK_, PW_, HID_);

    // 2) RMSNorm + RoPE in place on q,k      (one warp per token-head)
    norm_rope_kernel<<<(MTOK_ * 2 * H_) / 8, 256>>>(proj);

    // 3) scores = scale * q @ k^T            (causal tiles only)
    scores_kernel<<<dim3(L_ / 128, L_ / 128, B_ * H_), 256>>>(proj, scores);

    // 4) causal softmax rows
    softmax_kernel<<<B_ * H_ * L_, 256>>>(scores);

    // 5) attn = (P @ V) * sigmoid(gate)
    pv_kernel<<<dim3(L_ / 128, B_ * H_), 256>>>(proj, scores, attn);

    // 6) out = attn @ W_out
    sgemm_nn<<<dim3(HID_ / 128, MTOK_ / 128), 256>>>(
        attn, HID_, Wout, HID_, out, HID_, MTOK_, HID_, HID_);
}

// round 2
// speedup vs baseline: 2.9822x; 2.9822x over previous
#include <cuda_runtime.h>
#include <math.h>
#include <stdint.h>

#define B_    4
#define L_    2048
#define HID_  2048
#define H_    16
#define DH_   128
#define QKV_  (3 * HID_)          // 6144
#define PW_   (QKV_ + HID_)       // 8192
#define MTOK_ (B_ * L_)           // 8192
#define EPS_  1e-5f
#define SCALE_ 0.08838834764831845f   // 1/sqrt(128)

// Scratch (allocation-free rule: __device__ globals)
__device__ float g_proj[(size_t)MTOK_ * PW_];                 // 256 MB
__device__ float g_scores[(size_t)B_ * H_ * L_ * L_];         // 1 GB
__device__ float g_attn[(size_t)MTOK_ * HID_];                // 64 MB

__device__ __forceinline__ uint32_t f2tf(float x) {
    uint32_t u;
    asm("cvt.rna.tf32.f32 %0, %1;" : "=r"(u) : "f"(x));
    return u;
}

__device__ __forceinline__ void mma8(float* c, const uint32_t* a, const uint32_t* b) {
    asm volatile(
        "mma.sync.aligned.m16n8k8.row.col.f32.tf32.tf32.f32 "
        "{%0,%1,%2,%3}, {%4,%5,%6,%7}, {%8,%9}, {%0,%1,%2,%3};\n"
        : "+f"(c[0]), "+f"(c[1]), "+f"(c[2]), "+f"(c[3])
        : "r"(a[0]), "r"(a[1]), "r"(a[2]), "r"(a[3]), "r"(b[0]), "r"(b[1]));
}

// ---------------------------------------------------------------------------
// Unified tf32 tensor-core GEMM, 128x128x32 block tile, 256 threads.
// MODE 0: C = A*B (NN, row-major both), generic lda/ldb/ldc/K.
// MODE 2: scores = scale * Q @ K^T per (b,h); causal tile skip. z = bh.
// MODE 3: attn = (P @ V) * sigmoid(gate) per (b,h); K truncated causally.
// ---------------------------------------------------------------------------
template<int MODE>
__global__ __launch_bounds__(256) void gemm_tf32(
    const float* __restrict__ P0, const float* __restrict__ P1,
    float* __restrict__ P2, int lda, int ldb, int ldc, int K)
{
    constexpr bool NT = (MODE == 2);

    const int bx = blockIdx.x, by = blockIdx.y, z = blockIdx.z;
    const int m0 = by * 128, n0 = bx * 128;

    const float* Ap;
    const float* Bp;
    float* Cp;
    const float* Gp = nullptr;

    if (MODE == 0) {
        Ap = P0; Bp = P1; Cp = P2;
    } else if (MODE == 2) {
        if (n0 > m0) return;                       // above-diagonal tile
        const int b = z >> 4, h = z & 15;
        Ap = P0 + (size_t)b * L_ * PW_ + (size_t)h * DH_;          lda = PW_;
        Bp = P0 + (size_t)b * L_ * PW_ + (size_t)(H_ + h) * DH_;   ldb = PW_;
        Cp = P2 + (size_t)z * L_ * L_;                             ldc = L_;
        K = DH_;
    } else {  // MODE == 3
        const int b = z >> 4, h = z & 15;
        Ap = P0 + (size_t)z * L_ * L_;                             lda = L_;
        Bp = P1 + (size_t)b * L_ * PW_ + (size_t)(2 * H_ + h) * DH_; ldb = PW_;
        Gp = P1 + (size_t)b * L_ * PW_ + QKV_ + (size_t)h * DH_;
        Cp = P2 + (size_t)b * L_ * HID_ + (size_t)h * DH_;         ldc = HID_;
        K = m0 + 128;                               // causal truncation
    }

    __shared__ uint32_t As[128 * 36];               // [m][k], stride 36 (==4 mod 32)
    __shared__ uint32_t Bs[NT ? 128 * 36 : 32 * 136];

    const int tid = threadIdx.x;
    const int warp = tid >> 5, lane = tid & 31;
    const int wm = (warp >> 1) * 32;                // 4 warps along M
    const int wn = (warp & 1) * 64;                 // 2 warps along N
    const int lr = lane >> 2, lc = lane & 3;

    float acc[2][8][4];
#pragma unroll
    for (int mt = 0; mt < 2; mt++)
#pragma unroll
        for (int nt = 0; nt < 8; nt++)
#pragma unroll
            for (int i = 0; i < 4; i++) acc[mt][nt][i] = 0.f;

    const float* Abase = Ap + (size_t)m0 * lda;

    for (int k0 = 0; k0 < K; k0 += 32) {
        // --- load A tile 128x32 (row-major, tf32 convert at store) ---
#pragma unroll
        for (int i = 0; i < 4; i++) {
            const int idx = tid + i * 256;
            const int r = idx >> 3, q = (idx & 7) << 2;
            const float4 v = *(const float4*)(Abase + (size_t)r * lda + k0 + q);
            uint32_t* d = &As[r * 36 + q];
            d[0] = f2tf(v.x); d[1] = f2tf(v.y); d[2] = f2tf(v.z); d[3] = f2tf(v.w);
        }
        // --- load B tile ---
        if (NT) {
            // B rows indexed by n (K^T): Bs[n][k], 128x32, stride 36
#pragma unroll
            for (int i = 0; i < 4; i++) {
                const int idx = tid + i * 256;
                const int r = idx >> 3, q = (idx & 7) << 2;
                const float4 v = *(const float4*)(Bp + (size_t)(n0 + r) * ldb + k0 + q);
                uint32_t* d = &Bs[r * 36 + q];
                d[0] = f2tf(v.x); d[1] = f2tf(v.y); d[2] = f2tf(v.z); d[3] = f2tf(v.w);
            }
        } else {
            // Bs[k][n], 32x128, stride 136 (==8 mod 32)
#pragma unroll
            for (int i = 0; i < 4; i++) {
                const int idx = tid + i * 256;
                const int kr = idx >> 5, nq = (idx & 31) << 2;
                const float4 v = *(const float4*)(Bp + (size_t)(k0 + kr) * ldb + n0 + nq);
                uint32_t* d = &Bs[kr * 136 + nq];
                d[0] = f2tf(v.x); d[1] = f2tf(v.y); d[2] = f2tf(v.z); d[3] = f2tf(v.w);
            }
        }
        __syncthreads();

#pragma unroll
        for (int kk = 0; kk < 4; kk++) {
            const int k8 = kk * 8;
            uint32_t af[2][4];
#pragma unroll
            for (int mt = 0; mt < 2; mt++) {
                const int r = wm + mt * 16 + lr;
                af[mt][0] = As[r * 36 + k8 + lc];
                af[mt][1] = As[(r + 8) * 36 + k8 + lc];
                af[mt][2] = As[r * 36 + k8 + lc + 4];
                af[mt][3] = As[(r + 8) * 36 + k8 + lc + 4];
            }
            uint32_t bf[8][2];
#pragma unroll
            for (int nt = 0; nt < 8; nt++) {
                const int n = wn + nt * 8 + lr;
                if (NT) {
                    bf[nt][0] = Bs[n * 36 + k8 + lc];
                    bf[nt][1] = Bs[n * 36 + k8 + lc + 4];
                } else {
                    bf[nt][0] = Bs[(k8 + lc) * 136 + n];
                    bf[nt][1] = Bs[(k8 + lc + 4) * 136 + n];
                }
            }
#pragma unroll
            for (int mt = 0; mt < 2; mt++)
#pragma unroll
                for (int nt = 0; nt < 8; nt++)
                    mma8(acc[mt][nt], af[mt], bf[nt]);
        }
        __syncthreads();
    }

    // --- epilogue ---
#pragma unroll
    for (int mt = 0; mt < 2; mt++) {
#pragma unroll
        for (int nt = 0; nt < 8; nt++) {
            const int r = m0 + wm + mt * 16 + lr;
            const int c = n0 + wn + nt * 8 + lc * 2;
            float a0 = acc[mt][nt][0], a1 = acc[mt][nt][1];
            float a2 = acc[mt][nt][2], a3 = acc[mt][nt][3];
            if (MODE == 2) {
                a0 *= SCALE_; a1 *= SCALE_; a2 *= SCALE_; a3 *= SCALE_;
            }
            if (MODE == 3) {
                const float2 g0 = *(const float2*)(Gp + (size_t)r * PW_ + c);
                const float2 g1 = *(const float2*)(Gp + (size_t)(r + 8) * PW_ + c);
                a0 *= 1.f / (1.f + __expf(-g0.x));
                a1 *= 1.f / (1.f + __expf(-g0.y));
                a2 *= 1.f / (1.f + __expf(-g1.x));
                a3 *= 1.f / (1.f + __expf(-g1.y));
            }
            *(float2*)(Cp + (size_t)r * ldc + c) = make_float2(a0, a1);
            *(float2*)(Cp + (size_t)(r + 8) * ldc + c) = make_float2(a2, a3);
        }
    }
}

// ---------------------------------------------------------------------------
// RMSNorm + RoPE in place on q (heads 0..15) and k (heads 16..31) of g_proj.
// ---------------------------------------------------------------------------
__global__ __launch_bounds__(256) void norm_rope_kernel(float* __restrict__ proj)
{
    const int warp = blockIdx.x * 8 + (threadIdx.x >> 5);
    const int lane = threadIdx.x & 31;
    const int head2 = warp & 31;
    const int tok = warp >> 5;
    const int pos = tok & (L_ - 1);

    float* x = proj + (size_t)tok * PW_ + (size_t)head2 * DH_;
    float v0 = x[lane];
    float v1 = x[lane + 32];
    float v2 = x[lane + 64];
    float v3 = x[lane + 96];

    float ss = v0 * v0 + v1 * v1 + v2 * v2 + v3 * v3;
#pragma unroll
    for (int o = 16; o; o >>= 1) ss += __shfl_xor_sync(0xffffffffu, ss, o);
    const float r = rsqrtf(ss * (1.0f / DH_) + EPS_);
    v0 *= r; v1 *= r; v2 *= r; v3 *= r;

    const float kf = 9.210340371976184f / 64.0f;
    const float fpos = (float)pos;
    const float a0 = fpos * __expf(-kf * (float)lane);
    const float a1 = fpos * __expf(-kf * (float)(lane + 32));
    float c0, s0, c1, s1;
    sincosf(a0, &s0, &c0);
    sincosf(a1, &s1, &c1);

    x[lane]      = v0 * c0 - v2 * s0;
    x[lane + 64] = v0 * s0 + v2 * c0;
    x[lane + 32] = v1 * c1 - v3 * s1;
    x[lane + 96] = v1 * s1 + v3 * c1;
}

// ---------------------------------------------------------------------------
// Causal softmax per row, zero-padded to the row's 128-tile boundary.
// ---------------------------------------------------------------------------
__global__ __launch_bounds__(256) void softmax_kernel(float* __restrict__ S)
{
    const size_t row = blockIdx.x;
    const int i = (int)(row & (size_t)(L_ - 1));
    float* s = S + row * (size_t)L_;
    const int n = i + 1;
    const int tid = threadIdx.x;
    __shared__ float shm[8];

    float m = -3.402823e38f;
    for (int j = tid; j < n; j += 256) m = fmaxf(m, s[j]);
#pragma unroll
    for (int o = 16; o; o >>= 1) m = fmaxf(m, __shfl_xor_sync(0xffffffffu, m, o));
    if ((tid & 31) == 0) shm[tid >> 5] = m;
    __syncthreads();
    if (tid == 0) {
        float t = shm[0];
#pragma unroll
        for (int w = 1; w < 8; w++) t = fmaxf(t, shm[w]);
        shm[0] = t;
    }
    __syncthreads();
    const float mall = shm[0];
    __syncthreads();

    float sum = 0.f;
    for (int j = tid; j < n; j += 256) {
        float e = __expf(s[j] - mall);
        s[j] = e;
        sum += e;
    }
#pragma unroll
    for (int o = 16; o; o >>= 1) sum += __shfl_xor_sync(0xffffffffu, sum, o);
    if ((tid & 31) == 0) shm[tid >> 5] = sum;
    __syncthreads();
    if (tid == 0) {
        float t = 0.f;
#pragma unroll
        for (int w = 0; w < 8; w++) t += shm[w];
        shm[0] = t;
    }
    __syncthreads();
    const float inv = 1.0f / shm[0];

    for (int j = tid; j < n; j += 256) s[j] *= inv;

    const int pend = (i & ~127) + 128;
    for (int j = n + tid; j < pend; j += 256) s[j] = 0.f;
}

// ---------------------------------------------------------------------------
extern "C" void kernel_launch(void* const* d_in, const int* in_sizes, int n_in,
                              void* d_out, int out_size)
{
    const float* hidden = (const float*)d_in[0];   // [B,L,HID]
    const float* Wqkvg  = (const float*)d_in[1];   // [HID, PW]
    const float* Wout   = (const float*)d_in[2];   // [HID, HID]
    float* out = (float*)d_out;                    // [B,L,HID]

    float *proj, *scores, *attn;
    cudaGetSymbolAddress((void**)&proj,   g_proj);
    cudaGetSymbolAddress((void**)&scores, g_scores);
    cudaGetSymbolAddress((void**)&attn,   g_attn);

    // 1) proj = hidden @ W_qkvg
    gemm_tf32<0><<<dim3(PW_ / 128, MTOK_ / 128), 256>>>(
        hidden, Wqkvg, proj, HID_, PW_, PW_, HID_);

    // 2) RMSNorm + RoPE on q,k
    norm_rope_kernel<<<(MTOK_ * 2 * H_) / 8, 256>>>(proj);

    // 3) scores = scale * q @ k^T (causal tiles)
    gemm_tf32<2><<<dim3(L_ / 128, L_ / 128, B_ * H_), 256>>>(
        proj, nullptr, scores, 0, 0, 0, 0);

    // 4) causal softmax
    softmax_kernel<<<B_ * H_ * L_, 256>>>(scores);

    // 5) attn = (P @ V) * sigmoid(gate)
    gemm_tf32<3><<<dim3(1, L_ / 128, B_ * H_), 256>>>(
        scores, proj, attn, 0, 0, 0, 0);

    // 6) out = attn @ W_out
    gemm_tf32<0><<<dim3(HID_ / 128, MTOK_ / 128), 256>>>(
        attn, Wout, out, HID_, HID_, HID_, HID_);
}

// round 4
// speedup vs baseline: 3.4336x; 1.1514x over previous
#include <cuda_runtime.h>
#include <math.h>
#include <stdint.h>

#define B_    4
#define L_    2048
#define HID_  2048
#define H_    16
#define DH_   128
#define QKV_  (3 * HID_)          // 6144
#define PW_   (QKV_ + HID_)       // 8192
#define MTOK_ (B_ * L_)           // 8192
#define EPS_  1e-5f
#define SCALE_ 0.08838834764831845f   // 1/sqrt(128)
#define FULLM 0xffffffffu

// Scratch (allocation-free rule: __device__ globals)
__device__ float g_proj[(size_t)MTOK_ * PW_];                 // 256 MB
__device__ float g_attn[(size_t)MTOK_ * HID_];                // 64 MB

__device__ __forceinline__ uint32_t f2tf(float x) {
    uint32_t u;
    asm("cvt.rna.tf32.f32 %0, %1;" : "=r"(u) : "f"(x));
    return u;
}

__device__ __forceinline__ void mma8(float* c, const uint32_t* a, const uint32_t* b) {
    asm volatile(
        "mma.sync.aligned.m16n8k8.row.col.f32.tf32.tf32.f32 "
        "{%0,%1,%2,%3}, {%4,%5,%6,%7}, {%8,%9}, {%0,%1,%2,%3};\n"
        : "+f"(c[0]), "+f"(c[1]), "+f"(c[2]), "+f"(c[3])
        : "r"(a[0]), "r"(a[1]), "r"(a[2]), "r"(a[3]), "r"(b[0]), "r"(b[1]));
}

// ===========================================================================
// Double-buffered tf32 NN GEMM: C[M,N] = A[M,K] * B[K,N], 128x128x32 tile,
// 256 threads, register prefetch + 2-stage smem.
// ===========================================================================
#define ASTR 36
#define BSTR 136
#define ASZ  (128 * ASTR)   // u32 words
#define BSZ  (32 * BSTR)
#define GEMM_SMEM (2 * (ASZ + BSZ) * 4)

__global__ __launch_bounds__(256, 1) void gemm_nn_db(
    const float* __restrict__ A, int lda,
    const float* __restrict__ B, int ldb,
    float* __restrict__ C, int ldc, int K)
{
    extern __shared__ uint32_t sm[];
    uint32_t* As = sm;              // [2][128][36]
    uint32_t* Bs = sm + 2 * ASZ;    // [2][32][136]

    const int tid = threadIdx.x;
    const int m0 = blockIdx.y * 128, n0 = blockIdx.x * 128;
    const int warp = tid >> 5, lane = tid & 31;
    const int wm = (warp >> 1) * 32;
    const int wn = (warp & 1) * 64;
    const int lr = lane >> 2, lc = lane & 3;

    // load-index precompute
    const int rA = tid >> 3, qA = (tid & 7) * 4;        // A: r = rA+i*32
    const int kB = tid >> 5, nB = (tid & 31) * 4;       // B: k = kB+i*8

    float4 Ar[4], Br[4];
    const float* Abase = A + (size_t)m0 * lda;
    const float* Bbase = B + n0;

#define G2R(k0)                                                              \
    {                                                                        \
        _Pragma("unroll")                                                    \
        for (int i = 0; i < 4; i++) {                                        \
            Ar[i] = *(const float4*)(Abase + (size_t)(rA + i * 32) * lda + (k0) + qA); \
            Br[i] = *(const float4*)(Bbase + (size_t)((k0) + kB + i * 8) * ldb + nB);  \
        }                                                                    \
    }
#define R2S(p)                                                               \
    {                                                                        \
        uint32_t* a = As + (p) * ASZ;                                        \
        uint32_t* b = Bs + (p) * BSZ;                                        \
        _Pragma("unroll")                                                    \
        for (int i = 0; i < 4; i++) {                                        \
            uint32_t* d = &a[(rA + i * 32) * ASTR + qA];                     \
            d[0] = f2tf(Ar[i].x); d[1] = f2tf(Ar[i].y);                      \
            d[2] = f2tf(Ar[i].z); d[3] = f2tf(Ar[i].w);                      \
            uint32_t* e = &b[(kB + i * 8) * BSTR + nB];                      \
            e[0] = f2tf(Br[i].x); e[1] = f2tf(Br[i].y);                      \
            e[2] = f2tf(Br[i].z); e[3] = f2tf(Br[i].w);                      \
        }                                                                    \
    }

    float acc[2][8][4];
#pragma unroll
    for (int mt = 0; mt < 2; mt++)
#pragma unroll
        for (int nt = 0; nt < 8; nt++)
#pragma unroll
            for (int i = 0; i < 4; i++) acc[mt][nt][i] = 0.f;

    G2R(0);
    R2S(0);
    __syncthreads();

    int p = 0;
    for (int k0 = 0; k0 < K; k0 += 32) {
        const bool has_next = (k0 + 32 < K);
        if (has_next) G2R(k0 + 32);

        const uint32_t* a = As + p * ASZ;
        const uint32_t* b = Bs + p * BSZ;
#pragma unroll
        for (int kk = 0; kk < 4; kk++) {
            const int k8 = kk * 8;
            uint32_t af[2][4];
#pragma unroll
            for (int mt = 0; mt < 2; mt++) {
                const int r = wm + mt * 16 + lr;
                af[mt][0] = a[r * ASTR + k8 + lc];
                af[mt][1] = a[(r + 8) * ASTR + k8 + lc];
                af[mt][2] = a[r * ASTR + k8 + lc + 4];
                af[mt][3] = a[(r + 8) * ASTR + k8 + lc + 4];
            }
            uint32_t bf[8][2];
#pragma unroll
            for (int nt = 0; nt < 8; nt++) {
                const int n = wn + nt * 8 + lr;
                bf[nt][0] = b[(k8 + lc) * BSTR + n];
                bf[nt][1] = b[(k8 + lc + 4) * BSTR + n];
            }
#pragma unroll
            for (int mt = 0; mt < 2; mt++)
#pragma unroll
                for (int nt = 0; nt < 8; nt++)
                    mma8(acc[mt][nt], af[mt], bf[nt]);
        }

        if (has_next) {
            R2S(p ^ 1);
            __syncthreads();
        }
        p ^= 1;
    }

#pragma unroll
    for (int mt = 0; mt < 2; mt++)
#pragma unroll
        for (int nt = 0; nt < 8; nt++) {
            const int r = m0 + wm + mt * 16 + lr;
            const int c = n0 + wn + nt * 8 + lc * 2;
            *(float2*)(C + (size_t)r * ldc + c) =
                make_float2(acc[mt][nt][0], acc[mt][nt][1]);
            *(float2*)(C + (size_t)(r + 8) * ldc + c) =
                make_float2(acc[mt][nt][2], acc[mt][nt][3]);
        }
#undef G2R
#undef R2S
}

// ===========================================================================
// Flash attention (causal, online softmax) + sigmoid-gate epilogue.
// Block = one 128-row i-tile of one (b,h). 8 warps, warp owns 16 rows.
// ===========================================================================
#define QSTR 132
#define KSTR 132
#define VSTR 136
#define QSZ (128 * QSTR)
#define KSZ (128 * KSTR)
#define VSZ (128 * VSTR)
#define FLASH_SMEM ((QSZ + KSZ + VSZ) * 4)   // 204800 bytes

__global__ __launch_bounds__(256, 1) void flash_kernel(
    const float* __restrict__ proj, float* __restrict__ attn)
{
    extern __shared__ uint32_t sm[];
    uint32_t* Qs = sm;
    uint32_t* Ks = sm + QSZ;
    uint32_t* Vs = sm + QSZ + KSZ;

    const int it = blockIdx.x, bh = blockIdx.y;
    const int b = bh >> 4, h = bh & 15;
    const size_t base = (size_t)b * L_ * PW_;
    const float* Qp = proj + base + (size_t)h * DH_;
    const float* Kp = proj + base + (size_t)(H_ + h) * DH_;
    const float* Vp = proj + base + (size_t)(2 * H_ + h) * DH_;
    const float* Gp = proj + base + QKV_ + (size_t)h * DH_;
    float* Op = attn + (size_t)b * L_ * HID_ + (size_t)h * DH_;

    const int tid = threadIdx.x, warp = tid >> 5, lane = tid & 31;
    const int lr = lane >> 2, lc = lane & 3;
    const int wm = warp * 16;
    const int i0 = it * 128;

    // load Q once (scaled by 1/sqrt(DH), tf32): 16 float4 per thread
    const int qr = tid >> 5, qq = (tid & 31) * 4;
#pragma unroll
    for (int i = 0; i < 16; i++) {
        const int r = qr + i * 8;
        float4 v = *(const float4*)(Qp + (size_t)(i0 + r) * PW_ + qq);
        uint32_t* d = &Qs[r * QSTR + qq];
        d[0] = f2tf(v.x * SCALE_); d[1] = f2tf(v.y * SCALE_);
        d[2] = f2tf(v.z * SCALE_); d[3] = f2tf(v.w * SCALE_);
    }

    float m0v = -1e30f, m1v = -1e30f, l0 = 0.f, l1 = 0.f;
    float oacc[16][4];
#pragma unroll
    for (int nt = 0; nt < 16; nt++)
#pragma unroll
        for (int e = 0; e < 4; e++) oacc[nt][e] = 0.f;

    const int srcA = (lane & 28) | (lc >> 1);
    const int srcB = srcA + 2;
    const int r0g = i0 + wm + lr, r1g = r0g + 8;

    for (int jt = 0; jt <= it; ++jt) {
        const int j0 = jt * 128;
        // load K,V tiles (tf32)
#pragma unroll
        for (int i = 0; i < 16; i++) {
            const int r = qr + i * 8;
            float4 v = *(const float4*)(Kp + (size_t)(j0 + r) * PW_ + qq);
            uint32_t* d = &Ks[r * KSTR + qq];
            d[0] = f2tf(v.x); d[1] = f2tf(v.y); d[2] = f2tf(v.z); d[3] = f2tf(v.w);
            float4 w = *(const float4*)(Vp + (size_t)(j0 + r) * PW_ + qq);
            uint32_t* e = &Vs[r * VSTR + qq];
            e[0] = f2tf(w.x); e[1] = f2tf(w.y); e[2] = f2tf(w.z); e[3] = f2tf(w.w);
        }
        __syncthreads();

        // S = (Q*scale) @ K^T  (16x128 per warp)
        float sacc[16][4];
#pragma unroll
        for (int nt = 0; nt < 16; nt++)
#pragma unroll
            for (int e = 0; e < 4; e++) sacc[nt][e] = 0.f;

#pragma unroll
        for (int k8 = 0; k8 < 16; k8++) {
            const int kb = k8 * 8;
            uint32_t a[4];
            a[0] = Qs[(wm + lr) * QSTR + kb + lc];
            a[1] = Qs[(wm + lr + 8) * QSTR + kb + lc];
            a[2] = Qs[(wm + lr) * QSTR + kb + lc + 4];
            a[3] = Qs[(wm + lr + 8) * QSTR + kb + lc + 4];
#pragma unroll
            for (int nt = 0; nt < 16; nt++) {
                uint32_t bf[2];
                bf[0] = Ks[(nt * 8 + lr) * KSTR + kb + lc];
                bf[1] = Ks[(nt * 8 + lr) * KSTR + kb + lc + 4];
                mma8(sacc[nt], a, bf);
            }
        }

        // causal mask on the diagonal tile
        if (jt == it) {
#pragma unroll
            for (int nt = 0; nt < 16; nt++) {
                const int c0 = j0 + nt * 8 + 2 * lc;
                if (c0 > r0g)     sacc[nt][0] = -1e30f;
                if (c0 + 1 > r0g) sacc[nt][1] = -1e30f;
                if (c0 > r1g)     sacc[nt][2] = -1e30f;
                if (c0 + 1 > r1g) sacc[nt][3] = -1e30f;
            }
        }

        // online softmax stats (warp-local: quad reduce over lc)
        float tm0 = -1e30f, tm1 = -1e30f;
#pragma unroll
        for (int nt = 0; nt < 16; nt++) {
            tm0 = fmaxf(tm0, fmaxf(sacc[nt][0], sacc[nt][1]));
            tm1 = fmaxf(tm1, fmaxf(sacc[nt][2], sacc[nt][3]));
        }
        tm0 = fmaxf(tm0, __shfl_xor_sync(FULLM, tm0, 1));
        tm0 = fmaxf(tm0, __shfl_xor_sync(FULLM, tm0, 2));
        tm1 = fmaxf(tm1, __shfl_xor_sync(FULLM, tm1, 1));
        tm1 = fmaxf(tm1, __shfl_xor_sync(FULLM, tm1, 2));

        const float mn0 = fmaxf(m0v, tm0), mn1 = fmaxf(m1v, tm1);
        const float sc0 = __expf(m0v - mn0), sc1 = __expf(m1v - mn1);
        m0v = mn0; m1v = mn1;

        float rs0 = 0.f, rs1 = 0.f;
#pragma unroll
        for (int nt = 0; nt < 16; nt++) {
            float p0 = __expf(sacc[nt][0] - mn0);
            float p1 = __expf(sacc[nt][1] - mn0);
            float p2 = __expf(sacc[nt][2] - mn1);
            float p3 = __expf(sacc[nt][3] - mn1);
            rs0 += p0 + p1; rs1 += p2 + p3;
            sacc[nt][0] = __uint_as_float(f2tf(p0));
            sacc[nt][1] = __uint_as_float(f2tf(p1));
            sacc[nt][2] = __uint_as_float(f2tf(p2));
            sacc[nt][3] = __uint_as_float(f2tf(p3));
            oacc[nt][0] *= sc0; oacc[nt][1] *= sc0;
            oacc[nt][2] *= sc1; oacc[nt][3] *= sc1;
        }
        rs0 += __shfl_xor_sync(FULLM, rs0, 1);
        rs0 += __shfl_xor_sync(FULLM, rs0, 2);
        rs1 += __shfl_xor_sync(FULLM, rs1, 1);
        rs1 += __shfl_xor_sync(FULLM, rs1, 2);
        l0 = l0 * sc0 + rs0;
        l1 = l1 * sc1 + rs1;

        // O += P @ V  (A-frag built via quad shuffles from P tiles)
#pragma unroll
        for (int kk = 0; kk < 16; kk++) {
            float x0 = __shfl_sync(FULLM, sacc[kk][0], srcA);
            float x1 = __shfl_sync(FULLM, sacc[kk][1], srcA);
            float x2 = __shfl_sync(FULLM, sacc[kk][2], srcA);
            float x3 = __shfl_sync(FULLM, sacc[kk][3], srcA);
            float y0 = __shfl_sync(FULLM, sacc[kk][0], srcB);
            float y1 = __shfl_sync(FULLM, sacc[kk][1], srcB);
            float y2 = __shfl_sync(FULLM, sacc[kk][2], srcB);
            float y3 = __shfl_sync(FULLM, sacc[kk][3], srcB);
            const bool odd = lc & 1;
            uint32_t a[4];
            a[0] = __float_as_uint(odd ? x1 : x0);
            a[1] = __float_as_uint(odd ? x3 : x2);
            a[2] = __float_as_uint(odd ? y1 : y0);
            a[3] = __float_as_uint(odd ? y3 : y2);
            const int kb = kk * 8;
#pragma unroll
            for (int nt = 0; nt < 16; nt++) {
                uint32_t bf[2];
                bf[0] = Vs[(kb + lc) * VSTR + nt * 8 + lr];
                bf[1] = Vs[(kb + lc + 4) * VSTR + nt * 8 + lr];
                mma8(oacc[nt], a, bf);
            }
        }
        __syncthreads();
    }

    // epilogue: normalize, sigmoid gate, store
    const float inv0 = 1.f / l0, inv1 = 1.f / l1;
#pragma unroll
    for (int nt = 0; nt < 16; nt++) {
        const int c = nt * 8 + 2 * lc;
        const float2 g0 = *(const float2*)(Gp + (size_t)r0g * PW_ + c);
        const float2 g1 = *(const float2*)(Gp + (size_t)r1g * PW_ + c);
        float o0 = oacc[nt][0] * inv0 * (1.f / (1.f + __expf(-g0.x)));
        float o1 = oacc[nt][1] * inv0 * (1.f / (1.f + __expf(-g0.y)));
        float o2 = oacc[nt][2] * inv1 * (1.f / (1.f + __expf(-g1.x)));
        float o3 = oacc[nt][3] * inv1 * (1.f / (1.f + __expf(-g1.y)));
        *(float2*)(Op + (size_t)r0g * HID_ + c) = make_float2(o0, o1);
        *(float2*)(Op + (size_t)r1g * HID_ + c) = make_float2(o2, o3);
    }
}

// ===========================================================================
// RMSNorm + RoPE in place on q (heads 0..15) and k (heads 16..31) of g_proj.
// ===========================================================================
__global__ __launch_bounds__(256) void norm_rope_kernel(float* __restrict__ proj)
{
    const int warp = blockIdx.x * 8 + (threadIdx.x >> 5);
    const int lane = threadIdx.x & 31;
    const int head2 = warp & 31;
    const int tok = warp >> 5;
    const int pos = tok & (L_ - 1);

    float* x = proj + (size_t)tok * PW_ + (size_t)head2 * DH_;
    float v0 = x[lane];
    float v1 = x[lane + 32];
    float v2 = x[lane + 64];
    float v3 = x[lane + 96];

    float ss = v0 * v0 + v1 * v1 + v2 * v2 + v3 * v3;
#pragma unroll
    for (int o = 16; o; o >>= 1) ss += __shfl_xor_sync(FULLM, ss, o);
    const float r = rsqrtf(ss * (1.0f / DH_) + EPS_);
    v0 *= r; v1 *= r; v2 *= r; v3 *= r;

    const float kf = 9.210340371976184f / 64.0f;
    const float fpos = (float)pos;
    const float a0 = fpos * __expf(-kf * (float)lane);
    const float a1 = fpos * __expf(-kf * (float)(lane + 32));
    float c0, s0, c1, s1;
    sincosf(a0, &s0, &c0);
    sincosf(a1, &s1, &c1);

    x[lane]      = v0 * c0 - v2 * s0;
    x[lane + 64] = v0 * s0 + v2 * c0;
    x[lane + 32] = v1 * c1 - v3 * s1;
    x[lane + 96] = v1 * s1 + v3 * c1;
}

// ===========================================================================
extern "C" void kernel_launch(void* const* d_in, const int* in_sizes, int n_in,
                              void* d_out, int out_size)
{
    const float* hidden = (const float*)d_in[0];   // [B,L,HID]
    const float* Wqkvg  = (const float*)d_in[1];   // [HID, PW]
    const float* Wout   = (const float*)d_in[2];   // [HID, HID]
    float* out = (float*)d_out;                    // [B,L,HID]

    float *proj, *attn;
    cudaGetSymbolAddress((void**)&proj, g_proj);
    cudaGetSymbolAddress((void**)&attn, g_attn);

    cudaFuncSetAttribute(gemm_nn_db,
                         cudaFuncAttributeMaxDynamicSharedMemorySize, GEMM_SMEM);
    cudaFuncSetAttribute(flash_kernel,
                         cudaFuncAttributeMaxDynamicSharedMemorySize, FLASH_SMEM);

    // 1) proj = hidden @ W_qkvg
    gemm_nn_db<<<dim3(PW_ / 128, MTOK_ / 128), 256, GEMM_SMEM>>>(
        hidden, HID_, Wqkvg, PW_, proj, PW_, HID_);

    // 2) RMSNorm + RoPE on q,k
    norm_rope_kernel<<<(MTOK_ * 2 * H_) / 8, 256>>>(proj);

    // 3) fused flash attention + gate
    flash_kernel<<<dim3(L_ / 128, B_ * H_), 256, FLASH_SMEM>>>(proj, attn);

    // 4) out = attn @ W_out
    gemm_nn_db<<<dim3(HID_ / 128, MTOK_ / 128), 256, GEMM_SMEM>>>(
        attn, HID_, Wout, HID_, out, HID_, HID_);
}